// round 13
// baseline (speedup 1.0000x reference)
#include <cuda_runtime.h>
#include <cuda_fp16.h>

#define N 8192
#define NB 64
#define SJ 4
#define NCTA 544
#define NCHUNK 32
#define NCLS 100
#define MARGIN 0.5f

// smem offsets (bytes); 103 KB -> 2 CTAs/SM
#define SM_A      0          // 32 KB (i tile)
#define SM_B0     32768      // 32 KB
#define SM_B1     65536      // 32 KB
#define SM_AAUG   98304      // 128 x 16B
#define SM_BAUG0  100352     // 128 x 16B
#define SM_BAUG1  102400     // 128 x 16B
#define SM_LABJ0  104448     // int[128]
#define SM_LABJ1  104960     // int[128]
#define SMEM_TOTAL 105472

__device__ int      g_hist[NCHUNK * NCLS];
__device__ int      g_labS[N];         // sorted labels (ascending)
__device__ uint2    g_xh[N * 32];      // sorted fp16 rows
__device__ uint4    g_augA[N];         // [-sq/2, 1, 0...] (8 f16)
__device__ uint4    g_augB[N];         // [1, -sq/2, 0...]
__device__ unsigned g_maxpos[N];       // dist_ap bits (>=0: uint order == float order)
__device__ unsigned g_minneg[N];       // dist_an bits

// ---------------------------------------------------------------------------
// K0: per-chunk label histogram + accumulator init (sort-order independent)
// ---------------------------------------------------------------------------
__global__ void hist_kernel(const int* __restrict__ lab) {
    __shared__ int h[NCLS];
    int tid = threadIdx.x;
    int i = blockIdx.x * 256 + tid;
    if (tid < NCLS) h[tid] = 0;
    g_maxpos[i] = 0u;
    g_minneg[i] = __float_as_uint(1e30f);
    __syncthreads();
    atomicAdd(&h[lab[i]], 1);
    __syncthreads();
    if (tid < NCLS) g_hist[blockIdx.x * NCLS + tid] = h[tid];
}

// ---------------------------------------------------------------------------
// K1: rank (stable counting-sort position) + fused gathered fp16 convert.
// Each thread owns one original row: computes its sorted position, then
// converts/writes the row + aug + label directly to that position.
// ---------------------------------------------------------------------------
__global__ void rankconv_kernel(const float* __restrict__ x, const int* __restrict__ lab) {
    __shared__ int tot[NCLS];       // global class totals
    __shared__ int myoff[NCLS];     // this chunk's global base per class
    __shared__ int wcnt[8 * NCLS];  // per-warp class counts
    const int tid = threadIdx.x, b = blockIdx.x, gb = b * 256;

    for (int k = tid; k < 8 * NCLS; k += 256) wcnt[k] = 0;
    if (tid < NCLS) {
        int s = 0, mine = 0;
#pragma unroll 8
        for (int c = 0; c < NCHUNK; c++) {
            if (c == b) mine = s;
            s += g_hist[c * NCLS + tid];
        }
        tot[tid] = s;
        myoff[tid] = mine;
    }
    __syncthreads();
    if (tid < NCLS) {
        int base = 0;
        for (int k = 0; k < tid; k++) base += tot[k];
        myoff[tid] += base;
    }
    const int l = lab[gb + tid];
    const int w = tid >> 5;
    unsigned mask = __match_any_sync(0xffffffffu, l);
    int lr = __popc(mask & ((1u << (tid & 31)) - 1u));
    if (lr == 0) wcnt[w * NCLS + l] = __popc(mask);
    __syncthreads();
    int off = 0;
    for (int w2 = 0; w2 < w; w2++) off += wcnt[w2 * NCLS + l];
    const int pos = myoff[l] + off + lr;
    g_labS[pos] = l;

    // fused convert: this thread streams its own row -> sorted slot
    const float4* row = (const float4*)(x + (size_t)(gb + tid) * 128);
    uint4* dst = ((uint4*)g_xh) + (size_t)pos * 16;
    float s = 0.f;
#pragma unroll
    for (int c = 0; c < 16; c++) {
        float4 a = row[2 * c], bb = row[2 * c + 1];
        s += a.x * a.x + a.y * a.y + a.z * a.z + a.w * a.w;
        s += bb.x * bb.x + bb.y * bb.y + bb.z * bb.z + bb.w * bb.w;
        __half2 h0 = __floats2half2_rn(a.x, a.y),  h1 = __floats2half2_rn(a.z, a.w);
        __half2 h2 = __floats2half2_rn(bb.x, bb.y), h3 = __floats2half2_rn(bb.z, bb.w);
        uint4 o;
        o.x = *(unsigned*)&h0; o.y = *(unsigned*)&h1;
        o.z = *(unsigned*)&h2; o.w = *(unsigned*)&h3;
        dst[c] = o;
    }
    __half2 aA = __floats2half2_rn(-0.5f * s, 1.0f);
    __half2 aB = __floats2half2_rn(1.0f, -0.5f * s);
    uint4 u;
    u.y = 0; u.z = 0; u.w = 0;
    u.x = *(unsigned*)&aA; g_augA[pos] = u;
    u.x = *(unsigned*)&aB; g_augB[pos] = u;
}

// ---------------------------------------------------------------------------
// asm helpers
// ---------------------------------------------------------------------------
static __device__ __forceinline__ void ldm_x4(unsigned& r0, unsigned& r1,
                                              unsigned& r2, unsigned& r3, unsigned a) {
    asm volatile("ldmatrix.sync.aligned.m8n8.x4.shared.b16 {%0,%1,%2,%3}, [%4];"
                 : "=r"(r0), "=r"(r1), "=r"(r2), "=r"(r3) : "r"(a));
}
static __device__ __forceinline__ void ldm_x2(unsigned& r0, unsigned& r1, unsigned a) {
    asm volatile("ldmatrix.sync.aligned.m8n8.x2.shared.b16 {%0,%1}, [%2];"
                 : "=r"(r0), "=r"(r1) : "r"(a));
}
static __device__ __forceinline__ void mma16816(float* d, const unsigned* a, const unsigned* b) {
    asm volatile(
        "mma.sync.aligned.m16n8k16.row.col.f32.f16.f16.f32 "
        "{%0,%1,%2,%3}, {%4,%5,%6,%7}, {%8,%9}, {%0,%1,%2,%3};"
        : "+f"(d[0]), "+f"(d[1]), "+f"(d[2]), "+f"(d[3])
        : "r"(a[0]), "r"(a[1]), "r"(a[2]), "r"(a[3]), "r"(b[0]), "r"(b[1]));
}
static __device__ __forceinline__ void mma16808(float* d, const unsigned* a, unsigned b) {
    asm volatile(
        "mma.sync.aligned.m16n8k8.row.col.f32.f16.f16.f32 "
        "{%0,%1,%2,%3}, {%4,%5}, {%6}, {%0,%1,%2,%3};"
        : "+f"(d[0]), "+f"(d[1]), "+f"(d[2]), "+f"(d[3])
        : "r"(a[0]), "r"(a[1]), "r"(b));
}
static __device__ __forceinline__ void cpa16(unsigned dst, const void* src) {
    asm volatile("cp.async.cg.shared.global [%0], [%1], 16;" :: "r"(dst), "l"(src) : "memory");
}
static __device__ __forceinline__ void cpa4(unsigned dst, const void* src) {
    asm volatile("cp.async.ca.shared.global [%0], [%1], 4;" :: "r"(dst), "l"(src) : "memory");
}

// ---------------------------------------------------------------------------
// K2: triangular strips of 128x128 G-tiles (K = 128 + 8 aug), SJ=4.
// G = <xi,xj> - (sqi+sqj)/2 = -dist/2. Sorted labels -> disjoint-label tiles
// take the pure-negative fast path. 8 warps: 4(M) x 2(N), warp tile 32x64.
// ---------------------------------------------------------------------------
__global__ void __launch_bounds__(256, 2)
main_kernel() {
    extern __shared__ char smem[];
    unsigned sb;
    asm("{ .reg .u64 t; cvta.to.shared.u64 t, %1; cvt.u32.u64 %0, t; }"
        : "=r"(sb) : "l"(smem));

    const int tid  = threadIdx.x;
    const int lane = tid & 31;
    const int wid  = tid >> 5;
    const int wm   = wid & 3;
    const int wn   = wid >> 2;

    // block -> (bi, strip)
    int rem = blockIdx.x, bi = 0;
    while (rem >= ((NB - bi + SJ - 1) >> 2)) { rem -= (NB - bi + SJ - 1) >> 2; bi++; }
    const int bj0   = bi + rem * SJ;
    const int ntile = min(SJ, NB - bj0);
    const int i0    = bi * 128;

    const uint4* xh4 = (const uint4*)g_xh;

    // --- prologue: A + Aaug + B0 + Baug0 + labJ0 ---
#pragma unroll
    for (int t = 0; t < 8; t++) {
        int idx = tid + t * 256;
        int row = idx >> 4, c = idx & 15;
        cpa16(sb + SM_A + row * 256 + ((c ^ (row & 7)) << 4),
              &xh4[((size_t)(i0 + row) << 4) + c]);
    }
    {
        int j0 = bj0 * 128;
#pragma unroll
        for (int t = 0; t < 8; t++) {
            int idx = tid + t * 256;
            int row = idx >> 4, c = idx & 15;
            cpa16(sb + SM_B0 + row * 256 + ((c ^ (row & 7)) << 4),
                  &xh4[((size_t)(j0 + row) << 4) + c]);
        }
        if (tid < 128) {
            cpa16(sb + SM_AAUG + tid * 16, &g_augA[i0 + tid]);
            cpa16(sb + SM_BAUG0 + tid * 16, &g_augB[j0 + tid]);
            cpa4(sb + SM_LABJ0 + tid * 4, &g_labS[j0 + tid]);
        }
    }
    asm volatile("cp.async.commit_group;" ::: "memory");

    // ldmatrix addressing
    const int aRow0 = wm * 32 + (lane & 15);
    const unsigned aBase0 = sb + SM_A + aRow0 * 256;
    const unsigned aBase1 = aBase0 + 16 * 256;
    const int aSw0 = aRow0 & 7, aSw1 = (aRow0 + 16) & 7;
    const int aCb  = lane >> 4;
    const int bRowL = wn * 64 + (lane & 7) + ((lane >> 4) << 3);
    const int bCb   = (lane >> 3) & 1;

    // per-thread row labels (sorted) + strip accumulators
    int li[2][2];
#pragma unroll
    for (int mt = 0; mt < 2; mt++)
#pragma unroll
        for (int p = 0; p < 2; p++)
            li[mt][p] = g_labS[i0 + wm * 32 + mt * 16 + (lane >> 2) + p * 8];
    const int labLastI = g_labS[i0 + 127];

    float gP[2][2], gN[2][2];   // min G over positives / max G over negatives
#pragma unroll
    for (int mt = 0; mt < 2; mt++)
#pragma unroll
        for (int p = 0; p < 2; p++) { gP[mt][p] = 1e30f; gN[mt][p] = -1e30f; }

    unsigned aA[2][2];

    for (int t = 0; t < ntile; t++) {
        asm volatile("cp.async.wait_group 0;" ::: "memory");
        __syncthreads();

        if (t == 0) {   // A-aug fragments are strip-constant
            ldm_x2(aA[0][0], aA[0][1], sb + SM_AAUG + (wm * 32 + (lane & 15)) * 16);
            ldm_x2(aA[1][0], aA[1][1], sb + SM_AAUG + (wm * 32 + 16 + (lane & 15)) * 16);
        }

        // prefetch next tile
        if (t + 1 < ntile) {
            int jn = (bj0 + t + 1) * 128;
            unsigned bdst = sb + (((t + 1) & 1) ? SM_B1 : SM_B0);
#pragma unroll
            for (int u = 0; u < 8; u++) {
                int idx = tid + u * 256;
                int row = idx >> 4, c = idx & 15;
                cpa16(bdst + row * 256 + ((c ^ (row & 7)) << 4),
                      &xh4[((size_t)(jn + row) << 4) + c]);
            }
            if (tid < 128) {
                cpa16(sb + (((t + 1) & 1) ? SM_BAUG1 : SM_BAUG0) + tid * 16, &g_augB[jn + tid]);
                cpa4(sb + (((t + 1) & 1) ? SM_LABJ1 : SM_LABJ0) + tid * 4, &g_labS[jn + tid]);
            }
            asm volatile("cp.async.commit_group;" ::: "memory");
        }

        const unsigned bB    = sb + ((t & 1) ? SM_B1 : SM_B0);
        const unsigned bAug  = sb + ((t & 1) ? SM_BAUG1 : SM_BAUG0);
        const int*     labJ  = (const int*)(smem + ((t & 1) ? SM_LABJ1 : SM_LABJ0));
        const int      j0t   = (bj0 + t) * 128;
        const bool     slow  = (labLastI >= g_labS[j0t]);   // label ranges overlap

        // --- mainloop: 8x k16 + 1x k8 aug ---
        float d[2][8][4];
#pragma unroll
        for (int mt = 0; mt < 2; mt++)
#pragma unroll
            for (int nt = 0; nt < 8; nt++)
#pragma unroll
                for (int r = 0; r < 4; r++) d[mt][nt][r] = 0.f;

#pragma unroll
        for (int ks = 0; ks < 8; ks++) {
            unsigned a[2][4];
            ldm_x4(a[0][0], a[0][1], a[0][2], a[0][3],
                   aBase0 + (((2 * ks + aCb) ^ aSw0) << 4));
            ldm_x4(a[1][0], a[1][1], a[1][2], a[1][3],
                   aBase1 + (((2 * ks + aCb) ^ aSw1) << 4));
            unsigned b[8][2];
#pragma unroll
            for (int ntp = 0; ntp < 4; ntp++) {
                int row = bRowL + ntp * 16;
                unsigned addr = bB + row * 256 + (((2 * ks + bCb) ^ (row & 7)) << 4);
                ldm_x4(b[2 * ntp][0], b[2 * ntp][1], b[2 * ntp + 1][0], b[2 * ntp + 1][1], addr);
            }
#pragma unroll
            for (int mt = 0; mt < 2; mt++)
#pragma unroll
                for (int nt = 0; nt < 8; nt++)
                    mma16816(d[mt][nt], a[mt], b[nt]);
        }
        {   // aug k8 step: adds -(sqi+sqj)/2
            unsigned bA[8];
            ldm_x4(bA[0], bA[1], bA[2], bA[3], bAug + (wn * 64 + lane) * 16);
            ldm_x4(bA[4], bA[5], bA[6], bA[7], bAug + (wn * 64 + 32 + lane) * 16);
#pragma unroll
            for (int mt = 0; mt < 2; mt++)
#pragma unroll
                for (int nt = 0; nt < 8; nt++)
                    mma16808(d[mt][nt], aA[mt], bA[nt]);
        }

        // --- epilogue ---
        if (!slow) {
#pragma unroll
            for (int nt = 0; nt < 8; nt++) {
                float cx0 = -1e30f, cx1 = -1e30f;
#pragma unroll
                for (int mt = 0; mt < 2; mt++) {
                    gN[mt][0] = fmaxf(gN[mt][0], fmaxf(d[mt][nt][0], d[mt][nt][1]));
                    gN[mt][1] = fmaxf(gN[mt][1], fmaxf(d[mt][nt][2], d[mt][nt][3]));
                    cx0 = fmaxf(cx0, fmaxf(d[mt][nt][0], d[mt][nt][2]));
                    cx1 = fmaxf(cx1, fmaxf(d[mt][nt][1], d[mt][nt][3]));
                }
#pragma unroll
                for (int off = 4; off <= 16; off <<= 1) {
                    cx0 = fmaxf(cx0, __shfl_xor_sync(0xffffffffu, cx0, off));
                    cx1 = fmaxf(cx1, __shfl_xor_sync(0xffffffffu, cx1, off));
                }
                if (lane < 4) {
                    int j = j0t + wn * 64 + nt * 8 + lane * 2;
                    atomicMin(&g_minneg[j],     __float_as_uint(fmaxf(-2.f * cx0, 0.f)));
                    atomicMin(&g_minneg[j + 1], __float_as_uint(fmaxf(-2.f * cx1, 0.f)));
                }
            }
        } else {
#pragma unroll
            for (int nt = 0; nt < 8; nt++) {
                int colb = wn * 64 + nt * 8 + (lane & 3) * 2;
                int lj0 = labJ[colb], lj1 = labJ[colb + 1];
                float cx0 = -1e30f, cx1 = -1e30f, cn0 = 1e30f, cn1 = 1e30f;
#pragma unroll
                for (int mt = 0; mt < 2; mt++)
#pragma unroll
                    for (int r = 0; r < 4; r++) {
                        int q = r & 1, p = r >> 1;
                        float g = d[mt][nt][r];
                        if ((q ? lj1 : lj0) == li[mt][p]) {
                            gP[mt][p] = fminf(gP[mt][p], g);
                            if (q) cn1 = fminf(cn1, g); else cn0 = fminf(cn0, g);
                        } else {
                            gN[mt][p] = fmaxf(gN[mt][p], g);
                            if (q) cx1 = fmaxf(cx1, g); else cx0 = fmaxf(cx0, g);
                        }
                    }
#pragma unroll
                for (int off = 4; off <= 16; off <<= 1) {
                    cx0 = fmaxf(cx0, __shfl_xor_sync(0xffffffffu, cx0, off));
                    cx1 = fmaxf(cx1, __shfl_xor_sync(0xffffffffu, cx1, off));
                    cn0 = fminf(cn0, __shfl_xor_sync(0xffffffffu, cn0, off));
                    cn1 = fminf(cn1, __shfl_xor_sync(0xffffffffu, cn1, off));
                }
                if (lane < 4) {
                    int j = j0t + wn * 64 + nt * 8 + lane * 2;
                    atomicMin(&g_minneg[j],     __float_as_uint(fmaxf(-2.f * cx0, 0.f)));
                    atomicMin(&g_minneg[j + 1], __float_as_uint(fmaxf(-2.f * cx1, 0.f)));
                    atomicMax(&g_maxpos[j],     __float_as_uint(fmaxf(-2.f * cn0, 0.f)));
                    atomicMax(&g_maxpos[j + 1], __float_as_uint(fmaxf(-2.f * cn1, 0.f)));
                }
            }
        }
    }

    // --- row-side final: reduce lane&3, combine wn via smem overlay on A ---
#pragma unroll
    for (int mt = 0; mt < 2; mt++)
#pragma unroll
        for (int p = 0; p < 2; p++) {
#pragma unroll
            for (int off = 1; off <= 2; off <<= 1) {
                gN[mt][p] = fmaxf(gN[mt][p], __shfl_xor_sync(0xffffffffu, gN[mt][p], off));
                gP[mt][p] = fminf(gP[mt][p], __shfl_xor_sync(0xffffffffu, gP[mt][p], off));
            }
        }
    float* rP = (float*)(smem);          // [2][128]
    float* rN = (float*)(smem + 1024);   // [2][128]
    __syncthreads();   // everyone past mainloop; A region reusable
    if ((lane & 3) == 0) {
#pragma unroll
        for (int mt = 0; mt < 2; mt++)
#pragma unroll
            for (int p = 0; p < 2; p++) {
                int row = wm * 32 + mt * 16 + (lane >> 2) + p * 8;
                rP[wn * 128 + row] = gP[mt][p];
                rN[wn * 128 + row] = gN[mt][p];
            }
    }
    __syncthreads();
    if (tid < 128) {
        float gp = fminf(rP[tid], rP[128 + tid]);
        float gn = fmaxf(rN[tid], rN[128 + tid]);
        atomicMax(&g_maxpos[i0 + tid], __float_as_uint(fmaxf(-2.f * gp, 0.f)));
        atomicMin(&g_minneg[i0 + tid], __float_as_uint(fmaxf(-2.f * gn, 0.f)));
    }
}

// ---------------------------------------------------------------------------
// K3: loss = sum relu(maxpos - minneg + margin); deterministic single block
// ---------------------------------------------------------------------------
__global__ void final_kernel(float* __restrict__ out) {
    __shared__ float red[1024];
    float s = 0.f;
    for (int i = threadIdx.x; i < N; i += 1024) {
        float v = __uint_as_float(g_maxpos[i]) - __uint_as_float(g_minneg[i]) + MARGIN;
        s += fmaxf(v, 0.f);
    }
    red[threadIdx.x] = s;
    __syncthreads();
#pragma unroll
    for (int w = 512; w > 0; w >>= 1) {
        if (threadIdx.x < w) red[threadIdx.x] += red[threadIdx.x + w];
        __syncthreads();
    }
    if (threadIdx.x == 0) out[0] = red[0];
}

extern "C" void kernel_launch(void* const* d_in, const int* in_sizes, int n_in,
                              void* d_out, int out_size) {
    const float* x   = (const float*)d_in[0];
    const int*   lab = (const int*)d_in[1];
    float*       out = (float*)d_out;

    cudaFuncSetAttribute(main_kernel, cudaFuncAttributeMaxDynamicSharedMemorySize, SMEM_TOTAL);

    hist_kernel<<<NCHUNK, 256>>>(lab);
    rankconv_kernel<<<NCHUNK, 256>>>(x, lab);
    main_kernel<<<NCTA, 256, SMEM_TOTAL>>>();
    final_kernel<<<1, 1024>>>(out);
}

// round 14
// speedup vs baseline: 1.1371x; 1.1371x over previous
#include <cuda_runtime.h>
#include <cuda_fp16.h>

#define N 8192
#define NB 64
#define SJ 4
#define NCTA 544
#define NCHUNK 32
#define NCLS 100
#define MARGIN 0.5f

// smem offsets (bytes); 103 KB -> 2 CTAs/SM
#define SM_A      0          // 32 KB (i tile)
#define SM_B0     32768      // 32 KB
#define SM_B1     65536      // 32 KB
#define SM_AAUG   98304      // 128 x 16B
#define SM_BAUG0  100352     // 128 x 16B
#define SM_BAUG1  102400     // 128 x 16B
#define SM_LABJ0  104448     // int[128]
#define SM_LABJ1  104960     // int[128]
#define SMEM_TOTAL 105472

__device__ int      g_hist[NCHUNK * NCLS];
__device__ int      g_src[N];          // sorted pos -> original row
__device__ int      g_labS[N];         // sorted labels (ascending)
__device__ uint2    g_xh[N * 32];      // sorted fp16 rows
__device__ uint4    g_augA[N];         // [-sq/2, 1, 0...] (8 f16)
__device__ uint4    g_augB[N];         // [1, -sq/2, 0...]
__device__ uint2    g_mm[N];           // .x = maxpos bits, .y = minneg bits (>=0 floats)

// ---------------------------------------------------------------------------
// K0: per-chunk label histogram + accumulator init
// ---------------------------------------------------------------------------
__global__ void hist_kernel(const int* __restrict__ lab) {
    __shared__ int h[NCLS];
    int tid = threadIdx.x;
    int i = blockIdx.x * 256 + tid;
    if (tid < NCLS) h[tid] = 0;
    g_mm[i] = make_uint2(0u, __float_as_uint(1e30f));
    __syncthreads();
    atomicAdd(&h[lab[i]], 1);
    __syncthreads();
    if (tid < NCLS) g_hist[blockIdx.x * NCLS + tid] = h[tid];
}

// ---------------------------------------------------------------------------
// K1: stable counting-sort rank (match_any + per-warp counts)
// ---------------------------------------------------------------------------
__global__ void rank_kernel(const int* __restrict__ lab) {
    __shared__ int tot[NCLS];
    __shared__ int myoff[NCLS];
    __shared__ int wcnt[8 * NCLS];
    const int tid = threadIdx.x, b = blockIdx.x, gb = b * 256;

    for (int k = tid; k < 8 * NCLS; k += 256) wcnt[k] = 0;
    if (tid < NCLS) {
        int s = 0, mine = 0;
#pragma unroll 8
        for (int c = 0; c < NCHUNK; c++) {
            if (c == b) mine = s;
            s += g_hist[c * NCLS + tid];
        }
        tot[tid] = s;
        myoff[tid] = mine;
    }
    __syncthreads();
    if (tid < NCLS) {
        int base = 0;
        for (int k = 0; k < tid; k++) base += tot[k];
        myoff[tid] += base;
    }
    const int l = lab[gb + tid];
    const int w = tid >> 5;
    unsigned mask = __match_any_sync(0xffffffffu, l);
    int lr = __popc(mask & ((1u << (tid & 31)) - 1u));
    if (lr == 0) wcnt[w * NCLS + l] = __popc(mask);
    __syncthreads();
    int off = 0;
    for (int w2 = 0; w2 < w; w2++) off += wcnt[w2 * NCLS + l];
    int pos = myoff[l] + off + lr;
    g_src[pos] = gb + tid;
    g_labS[pos] = l;
}

// ---------------------------------------------------------------------------
// K2: gathered fp16 convert + norms + aug rows (16 coalesced threads/row)
// ---------------------------------------------------------------------------
__global__ void convert_kernel(const float* __restrict__ x) {
    int t = blockIdx.x * blockDim.x + threadIdx.x;
    int p = t >> 4, q = t & 15;
    int src = g_src[p];
    const float4* row = (const float4*)(x + (size_t)src * 128);
    float4 a = row[2 * q], b = row[2 * q + 1];
    float s = a.x * a.x + a.y * a.y + a.z * a.z + a.w * a.w
            + b.x * b.x + b.y * b.y + b.z * b.z + b.w * b.w;
    __half2 h0 = __floats2half2_rn(a.x, a.y), h1 = __floats2half2_rn(a.z, a.w);
    __half2 h2 = __floats2half2_rn(b.x, b.y), h3 = __floats2half2_rn(b.z, b.w);
    uint4 o;
    o.x = *(unsigned*)&h0; o.y = *(unsigned*)&h1;
    o.z = *(unsigned*)&h2; o.w = *(unsigned*)&h3;
    ((uint4*)g_xh)[(size_t)p * 16 + q] = o;
#pragma unroll
    for (int off = 1; off <= 8; off <<= 1)
        s += __shfl_xor_sync(0xffffffffu, s, off);
    if (q == 0) {
        __half2 aA = __floats2half2_rn(-0.5f * s, 1.0f);
        __half2 aB = __floats2half2_rn(1.0f, -0.5f * s);
        uint4 u;
        u.y = 0; u.z = 0; u.w = 0;
        u.x = *(unsigned*)&aA; g_augA[p] = u;
        u.x = *(unsigned*)&aB; g_augB[p] = u;
    }
}

// ---------------------------------------------------------------------------
// asm helpers
// ---------------------------------------------------------------------------
static __device__ __forceinline__ void ldm_x4(unsigned& r0, unsigned& r1,
                                              unsigned& r2, unsigned& r3, unsigned a) {
    asm volatile("ldmatrix.sync.aligned.m8n8.x4.shared.b16 {%0,%1,%2,%3}, [%4];"
                 : "=r"(r0), "=r"(r1), "=r"(r2), "=r"(r3) : "r"(a));
}
static __device__ __forceinline__ void ldm_x2(unsigned& r0, unsigned& r1, unsigned a) {
    asm volatile("ldmatrix.sync.aligned.m8n8.x2.shared.b16 {%0,%1}, [%2];"
                 : "=r"(r0), "=r"(r1) : "r"(a));
}
static __device__ __forceinline__ void mma16816(float* d, const unsigned* a, const unsigned* b) {
    asm volatile(
        "mma.sync.aligned.m16n8k16.row.col.f32.f16.f16.f32 "
        "{%0,%1,%2,%3}, {%4,%5,%6,%7}, {%8,%9}, {%0,%1,%2,%3};"
        : "+f"(d[0]), "+f"(d[1]), "+f"(d[2]), "+f"(d[3])
        : "r"(a[0]), "r"(a[1]), "r"(a[2]), "r"(a[3]), "r"(b[0]), "r"(b[1]));
}
static __device__ __forceinline__ void mma16808(float* d, const unsigned* a, unsigned b) {
    asm volatile(
        "mma.sync.aligned.m16n8k8.row.col.f32.f16.f16.f32 "
        "{%0,%1,%2,%3}, {%4,%5}, {%6}, {%0,%1,%2,%3};"
        : "+f"(d[0]), "+f"(d[1]), "+f"(d[2]), "+f"(d[3])
        : "r"(a[0]), "r"(a[1]), "r"(b));
}
static __device__ __forceinline__ void cpa16(unsigned dst, const void* src) {
    asm volatile("cp.async.cg.shared.global [%0], [%1], 16;" :: "r"(dst), "l"(src) : "memory");
}
static __device__ __forceinline__ void cpa4(unsigned dst, const void* src) {
    asm volatile("cp.async.ca.shared.global [%0], [%1], 4;" :: "r"(dst), "l"(src) : "memory");
}

// ---------------------------------------------------------------------------
// K3: triangular strips of 128x128 G-tiles (K = 128 + 8 aug), SJ=4.
// G = <xi,xj> - (sqi+sqj)/2 = -dist/2. Sorted labels -> disjoint-label tiles
// take the pure-negative fast path. 8 warps: 4(M) x 2(N), warp tile 32x64.
// ---------------------------------------------------------------------------
__global__ void __launch_bounds__(256, 2)
main_kernel() {
    extern __shared__ char smem[];
    unsigned sb;
    asm("{ .reg .u64 t; cvta.to.shared.u64 t, %1; cvt.u32.u64 %0, t; }"
        : "=r"(sb) : "l"(smem));

    const int tid  = threadIdx.x;
    const int lane = tid & 31;
    const int wid  = tid >> 5;
    const int wm   = wid & 3;
    const int wn   = wid >> 2;

    // block -> (bi, strip)
    int rem = blockIdx.x, bi = 0;
    while (rem >= ((NB - bi + SJ - 1) >> 2)) { rem -= (NB - bi + SJ - 1) >> 2; bi++; }
    const int bj0   = bi + rem * SJ;
    const int ntile = min(SJ, NB - bj0);
    const int i0    = bi * 128;

    const uint4* xh4 = (const uint4*)g_xh;

    // --- prologue: A + Aaug + B0 + Baug0 + labJ0 ---
#pragma unroll
    for (int t = 0; t < 8; t++) {
        int idx = tid + t * 256;
        int row = idx >> 4, c = idx & 15;
        cpa16(sb + SM_A + row * 256 + ((c ^ (row & 7)) << 4),
              &xh4[((size_t)(i0 + row) << 4) + c]);
    }
    {
        int j0 = bj0 * 128;
#pragma unroll
        for (int t = 0; t < 8; t++) {
            int idx = tid + t * 256;
            int row = idx >> 4, c = idx & 15;
            cpa16(sb + SM_B0 + row * 256 + ((c ^ (row & 7)) << 4),
                  &xh4[((size_t)(j0 + row) << 4) + c]);
        }
        if (tid < 128) {
            cpa16(sb + SM_AAUG + tid * 16, &g_augA[i0 + tid]);
            cpa16(sb + SM_BAUG0 + tid * 16, &g_augB[j0 + tid]);
            cpa4(sb + SM_LABJ0 + tid * 4, &g_labS[j0 + tid]);
        }
    }
    asm volatile("cp.async.commit_group;" ::: "memory");

    // ldmatrix addressing
    const int aRow0 = wm * 32 + (lane & 15);
    const unsigned aBase0 = sb + SM_A + aRow0 * 256;
    const unsigned aBase1 = aBase0 + 16 * 256;
    const int aSw0 = aRow0 & 7, aSw1 = (aRow0 + 16) & 7;
    const int aCb  = lane >> 4;
    const int bRowL = wn * 64 + (lane & 7) + ((lane >> 4) << 3);
    const int bCb   = (lane >> 3) & 1;

    // per-thread row labels (sorted) + strip accumulators
    int li[2][2];
#pragma unroll
    for (int mt = 0; mt < 2; mt++)
#pragma unroll
        for (int p = 0; p < 2; p++)
            li[mt][p] = g_labS[i0 + wm * 32 + mt * 16 + (lane >> 2) + p * 8];
    const int labLastI = g_labS[i0 + 127];

    float gP[2][2], gN[2][2];   // min G over positives / max G over negatives
#pragma unroll
    for (int mt = 0; mt < 2; mt++)
#pragma unroll
        for (int p = 0; p < 2; p++) { gP[mt][p] = 1e30f; gN[mt][p] = -1e30f; }

    unsigned aA[2][2];

    for (int t = 0; t < ntile; t++) {
        asm volatile("cp.async.wait_group 0;" ::: "memory");
        __syncthreads();

        if (t == 0) {   // A-aug fragments are strip-constant
            ldm_x2(aA[0][0], aA[0][1], sb + SM_AAUG + (wm * 32 + (lane & 15)) * 16);
            ldm_x2(aA[1][0], aA[1][1], sb + SM_AAUG + (wm * 32 + 16 + (lane & 15)) * 16);
        }

        // prefetch next tile
        if (t + 1 < ntile) {
            int jn = (bj0 + t + 1) * 128;
            unsigned bdst = sb + (((t + 1) & 1) ? SM_B1 : SM_B0);
#pragma unroll
            for (int u = 0; u < 8; u++) {
                int idx = tid + u * 256;
                int row = idx >> 4, c = idx & 15;
                cpa16(bdst + row * 256 + ((c ^ (row & 7)) << 4),
                      &xh4[((size_t)(jn + row) << 4) + c]);
            }
            if (tid < 128) {
                cpa16(sb + (((t + 1) & 1) ? SM_BAUG1 : SM_BAUG0) + tid * 16, &g_augB[jn + tid]);
                cpa4(sb + (((t + 1) & 1) ? SM_LABJ1 : SM_LABJ0) + tid * 4, &g_labS[jn + tid]);
            }
            asm volatile("cp.async.commit_group;" ::: "memory");
        }

        const unsigned bB    = sb + ((t & 1) ? SM_B1 : SM_B0);
        const unsigned bAug  = sb + ((t & 1) ? SM_BAUG1 : SM_BAUG0);
        const int*     labJ  = (const int*)(smem + ((t & 1) ? SM_LABJ1 : SM_LABJ0));
        const int      j0t   = (bj0 + t) * 128;
        const bool     slow  = (labLastI >= g_labS[j0t]);   // label ranges overlap

        // --- mainloop: 8x k16 + 1x k8 aug ---
        float d[2][8][4];
#pragma unroll
        for (int mt = 0; mt < 2; mt++)
#pragma unroll
            for (int nt = 0; nt < 8; nt++)
#pragma unroll
                for (int r = 0; r < 4; r++) d[mt][nt][r] = 0.f;

#pragma unroll
        for (int ks = 0; ks < 8; ks++) {
            unsigned a[2][4];
            ldm_x4(a[0][0], a[0][1], a[0][2], a[0][3],
                   aBase0 + (((2 * ks + aCb) ^ aSw0) << 4));
            ldm_x4(a[1][0], a[1][1], a[1][2], a[1][3],
                   aBase1 + (((2 * ks + aCb) ^ aSw1) << 4));
            unsigned b[8][2];
#pragma unroll
            for (int ntp = 0; ntp < 4; ntp++) {
                int row = bRowL + ntp * 16;
                unsigned addr = bB + row * 256 + (((2 * ks + bCb) ^ (row & 7)) << 4);
                ldm_x4(b[2 * ntp][0], b[2 * ntp][1], b[2 * ntp + 1][0], b[2 * ntp + 1][1], addr);
            }
#pragma unroll
            for (int mt = 0; mt < 2; mt++)
#pragma unroll
                for (int nt = 0; nt < 8; nt++)
                    mma16816(d[mt][nt], a[mt], b[nt]);
        }
        {   // aug k8 step: adds -(sqi+sqj)/2
            unsigned bA[8];
            ldm_x4(bA[0], bA[1], bA[2], bA[3], bAug + (wn * 64 + lane) * 16);
            ldm_x4(bA[4], bA[5], bA[6], bA[7], bAug + (wn * 64 + 32 + lane) * 16);
#pragma unroll
            for (int mt = 0; mt < 2; mt++)
#pragma unroll
                for (int nt = 0; nt < 8; nt++)
                    mma16808(d[mt][nt], aA[mt], bA[nt]);
        }

        // --- epilogue ---
        if (!slow) {
#pragma unroll
            for (int nt = 0; nt < 8; nt++) {
                float cx0 = -1e30f, cx1 = -1e30f;
#pragma unroll
                for (int mt = 0; mt < 2; mt++) {
                    gN[mt][0] = fmaxf(gN[mt][0], fmaxf(d[mt][nt][0], d[mt][nt][1]));
                    gN[mt][1] = fmaxf(gN[mt][1], fmaxf(d[mt][nt][2], d[mt][nt][3]));
                    cx0 = fmaxf(cx0, fmaxf(d[mt][nt][0], d[mt][nt][2]));
                    cx1 = fmaxf(cx1, fmaxf(d[mt][nt][1], d[mt][nt][3]));
                }
#pragma unroll
                for (int off = 4; off <= 16; off <<= 1) {
                    cx0 = fmaxf(cx0, __shfl_xor_sync(0xffffffffu, cx0, off));
                    cx1 = fmaxf(cx1, __shfl_xor_sync(0xffffffffu, cx1, off));
                }
                if (lane < 4) {
                    int j = j0t + wn * 64 + nt * 8 + lane * 2;
                    atomicMin(&g_mm[j].y,     __float_as_uint(fmaxf(-2.f * cx0, 0.f)));
                    atomicMin(&g_mm[j + 1].y, __float_as_uint(fmaxf(-2.f * cx1, 0.f)));
                }
            }
        } else {
#pragma unroll
            for (int nt = 0; nt < 8; nt++) {
                int colb = wn * 64 + nt * 8 + (lane & 3) * 2;
                int lj0 = labJ[colb], lj1 = labJ[colb + 1];
                float cx0 = -1e30f, cx1 = -1e30f, cn0 = 1e30f, cn1 = 1e30f;
#pragma unroll
                for (int mt = 0; mt < 2; mt++)
#pragma unroll
                    for (int r = 0; r < 4; r++) {
                        int q = r & 1, p = r >> 1;
                        float g = d[mt][nt][r];
                        if ((q ? lj1 : lj0) == li[mt][p]) {
                            gP[mt][p] = fminf(gP[mt][p], g);
                            if (q) cn1 = fminf(cn1, g); else cn0 = fminf(cn0, g);
                        } else {
                            gN[mt][p] = fmaxf(gN[mt][p], g);
                            if (q) cx1 = fmaxf(cx1, g); else cx0 = fmaxf(cx0, g);
                        }
                    }
#pragma unroll
                for (int off = 4; off <= 16; off <<= 1) {
                    cx0 = fmaxf(cx0, __shfl_xor_sync(0xffffffffu, cx0, off));
                    cx1 = fmaxf(cx1, __shfl_xor_sync(0xffffffffu, cx1, off));
                    cn0 = fminf(cn0, __shfl_xor_sync(0xffffffffu, cn0, off));
                    cn1 = fminf(cn1, __shfl_xor_sync(0xffffffffu, cn1, off));
                }
                if (lane < 4) {
                    int j = j0t + wn * 64 + nt * 8 + lane * 2;
                    atomicMin(&g_mm[j].y,     __float_as_uint(fmaxf(-2.f * cx0, 0.f)));
                    atomicMin(&g_mm[j + 1].y, __float_as_uint(fmaxf(-2.f * cx1, 0.f)));
                    atomicMax(&g_mm[j].x,     __float_as_uint(fmaxf(-2.f * cn0, 0.f)));
                    atomicMax(&g_mm[j + 1].x, __float_as_uint(fmaxf(-2.f * cn1, 0.f)));
                }
            }
        }
    }

    // --- row-side final: reduce lane&3, combine wn via smem overlay on A ---
#pragma unroll
    for (int mt = 0; mt < 2; mt++)
#pragma unroll
        for (int p = 0; p < 2; p++) {
#pragma unroll
            for (int off = 1; off <= 2; off <<= 1) {
                gN[mt][p] = fmaxf(gN[mt][p], __shfl_xor_sync(0xffffffffu, gN[mt][p], off));
                gP[mt][p] = fminf(gP[mt][p], __shfl_xor_sync(0xffffffffu, gP[mt][p], off));
            }
        }
    float* rP = (float*)(smem);          // [2][128]
    float* rN = (float*)(smem + 1024);   // [2][128]
    __syncthreads();   // everyone past mainloop; A region reusable
    if ((lane & 3) == 0) {
#pragma unroll
        for (int mt = 0; mt < 2; mt++)
#pragma unroll
            for (int p = 0; p < 2; p++) {
                int row = wm * 32 + mt * 16 + (lane >> 2) + p * 8;
                rP[wn * 128 + row] = gP[mt][p];
                rN[wn * 128 + row] = gN[mt][p];
            }
    }
    __syncthreads();
    if (tid < 128) {
        float gp = fminf(rP[tid], rP[128 + tid]);
        float gn = fmaxf(rN[tid], rN[128 + tid]);
        atomicMax(&g_mm[i0 + tid].x, __float_as_uint(fmaxf(-2.f * gp, 0.f)));
        atomicMin(&g_mm[i0 + tid].y, __float_as_uint(fmaxf(-2.f * gn, 0.f)));
    }
}

// ---------------------------------------------------------------------------
// K4: loss = sum relu(maxpos - minneg + margin); deterministic single block
// ---------------------------------------------------------------------------
__global__ void final_kernel(float* __restrict__ out) {
    __shared__ float red[1024];
    float s = 0.f;
    for (int i = threadIdx.x; i < N; i += 1024) {
        uint2 mm = g_mm[i];
        float v = __uint_as_float(mm.x) - __uint_as_float(mm.y) + MARGIN;
        s += fmaxf(v, 0.f);
    }
    red[threadIdx.x] = s;
    __syncthreads();
#pragma unroll
    for (int w = 512; w > 0; w >>= 1) {
        if (threadIdx.x < w) red[threadIdx.x] += red[threadIdx.x + w];
        __syncthreads();
    }
    if (threadIdx.x == 0) out[0] = red[0];
}

extern "C" void kernel_launch(void* const* d_in, const int* in_sizes, int n_in,
                              void* d_out, int out_size) {
    const float* x   = (const float*)d_in[0];
    const int*   lab = (const int*)d_in[1];
    float*       out = (float*)d_out;

    cudaFuncSetAttribute(main_kernel, cudaFuncAttributeMaxDynamicSharedMemorySize, SMEM_TOTAL);

    hist_kernel<<<NCHUNK, 256>>>(lab);
    rank_kernel<<<NCHUNK, 256>>>(lab);
    convert_kernel<<<N * 16 / 256, 256>>>(x);
    main_kernel<<<NCTA, 256, SMEM_TOTAL>>>();
    final_kernel<<<1, 1024>>>(out);
}

// round 15
// speedup vs baseline: 1.2003x; 1.0556x over previous
#include <cuda_runtime.h>
#include <cuda_fp16.h>

#define N 8192
#define NB 64
#define SJ 4
#define NCTA 544
#define NCHUNK 32
#define NCLS 100
#define MARGIN 0.5f

// smem offsets (bytes); 103 KB -> 2 CTAs/SM
#define SM_A      0          // 32 KB (i tile)
#define SM_B0     32768      // 32 KB
#define SM_B1     65536      // 32 KB
#define SM_AAUG   98304      // 128 x 16B
#define SM_BAUG0  100352     // 128 x 16B
#define SM_BAUG1  102400     // 128 x 16B
#define SM_LABJ0  104448     // int[128]
#define SM_LABJ1  104960     // int[128]
#define SMEM_TOTAL 105472

__device__ int      g_hist[NCHUNK * NCLS];
__device__ int      g_pos[N];          // original row -> sorted pos
__device__ int      g_labS[N];         // sorted labels (ascending)
__device__ uint2    g_xh[N * 32];      // sorted fp16 rows
__device__ uint4    g_augA[N];         // [-sq/2, 1, 0...] (8 f16)
__device__ uint4    g_augB[N];         // [1, -sq/2, 0...]
__device__ uint2    g_mm[N];           // .x = maxpos bits, .y = minneg bits (>=0 floats)

// ---------------------------------------------------------------------------
// K0: per-chunk label histogram + accumulator init
// ---------------------------------------------------------------------------
__global__ void hist_kernel(const int* __restrict__ lab) {
    __shared__ int h[NCLS];
    int tid = threadIdx.x;
    int i = blockIdx.x * 256 + tid;
    if (tid < NCLS) h[tid] = 0;
    g_mm[i] = make_uint2(0u, __float_as_uint(1e30f));
    __syncthreads();
    atomicAdd(&h[lab[i]], 1);
    __syncthreads();
    if (tid < NCLS) g_hist[blockIdx.x * NCLS + tid] = h[tid];
}

// ---------------------------------------------------------------------------
// K1: stable counting-sort rank; writes sorted labels + inverse map g_pos
// (PDL secondary: syncs on hist before reading g_hist)
// ---------------------------------------------------------------------------
__global__ void rank_kernel(const int* __restrict__ lab) {
    __shared__ int tot[NCLS];
    __shared__ int myoff[NCLS];
    __shared__ int wcnt[8 * NCLS];
    const int tid = threadIdx.x, b = blockIdx.x, gb = b * 256;

    // pre-sync: zero smem + read own labels (independent of hist)
    for (int k = tid; k < 8 * NCLS; k += 256) wcnt[k] = 0;
    const int l = lab[gb + tid];
    const int w = tid >> 5;

    cudaGridDependencySynchronize();   // g_hist ready

    if (tid < NCLS) {
        int s = 0, mine = 0;
#pragma unroll 8
        for (int c = 0; c < NCHUNK; c++) {
            if (c == b) mine = s;
            s += g_hist[c * NCLS + tid];
        }
        tot[tid] = s;
        myoff[tid] = mine;
    }
    __syncthreads();
    if (tid < NCLS) {
        int base = 0;
        for (int k = 0; k < tid; k++) base += tot[k];
        myoff[tid] += base;
    }
    unsigned mask = __match_any_sync(0xffffffffu, l);
    int lr = __popc(mask & ((1u << (tid & 31)) - 1u));
    if (lr == 0) wcnt[w * NCLS + l] = __popc(mask);
    __syncthreads();
    int off = 0;
    for (int w2 = 0; w2 < w; w2++) off += wcnt[w2 * NCLS + l];
    int pos = myoff[l] + off + lr;
    g_pos[gb + tid] = pos;
    g_labS[pos] = l;
}

// ---------------------------------------------------------------------------
// K2: fp16 convert + norms + aug rows (16 threads per ORIGINAL row).
// PDL secondary to rank: phase-1 (x load/convert/norm) runs concurrently
// with rank; only the scatter-write needs g_pos.
// ---------------------------------------------------------------------------
__global__ void convert_kernel(const float* __restrict__ x) {
    int t = blockIdx.x * blockDim.x + threadIdx.x;
    int r = t >> 4, q = t & 15;        // original row r, chunk q
    const float4* row = (const float4*)(x + (size_t)r * 128);
    float4 a = row[2 * q], b = row[2 * q + 1];
    float s = a.x * a.x + a.y * a.y + a.z * a.z + a.w * a.w
            + b.x * b.x + b.y * b.y + b.z * b.z + b.w * b.w;
    __half2 h0 = __floats2half2_rn(a.x, a.y), h1 = __floats2half2_rn(a.z, a.w);
    __half2 h2 = __floats2half2_rn(b.x, b.y), h3 = __floats2half2_rn(b.z, b.w);
    uint4 o;
    o.x = *(unsigned*)&h0; o.y = *(unsigned*)&h1;
    o.z = *(unsigned*)&h2; o.w = *(unsigned*)&h3;
#pragma unroll
    for (int off = 1; off <= 8; off <<= 1)
        s += __shfl_xor_sync(0xffffffffu, s, off);

    cudaGridDependencySynchronize();   // g_pos ready

    int pos = g_pos[r];                // broadcast across the 16-lane group
    ((uint4*)g_xh)[(size_t)pos * 16 + q] = o;
    if (q == 0) {
        __half2 aA = __floats2half2_rn(-0.5f * s, 1.0f);
        __half2 aB = __floats2half2_rn(1.0f, -0.5f * s);
        uint4 u;
        u.y = 0; u.z = 0; u.w = 0;
        u.x = *(unsigned*)&aA; g_augA[pos] = u;
        u.x = *(unsigned*)&aB; g_augB[pos] = u;
    }
}

// ---------------------------------------------------------------------------
// asm helpers
// ---------------------------------------------------------------------------
static __device__ __forceinline__ void ldm_x4(unsigned& r0, unsigned& r1,
                                              unsigned& r2, unsigned& r3, unsigned a) {
    asm volatile("ldmatrix.sync.aligned.m8n8.x4.shared.b16 {%0,%1,%2,%3}, [%4];"
                 : "=r"(r0), "=r"(r1), "=r"(r2), "=r"(r3) : "r"(a));
}
static __device__ __forceinline__ void ldm_x2(unsigned& r0, unsigned& r1, unsigned a) {
    asm volatile("ldmatrix.sync.aligned.m8n8.x2.shared.b16 {%0,%1}, [%2];"
                 : "=r"(r0), "=r"(r1) : "r"(a));
}
static __device__ __forceinline__ void mma16816(float* d, const unsigned* a, const unsigned* b) {
    asm volatile(
        "mma.sync.aligned.m16n8k16.row.col.f32.f16.f16.f32 "
        "{%0,%1,%2,%3}, {%4,%5,%6,%7}, {%8,%9}, {%0,%1,%2,%3};"
        : "+f"(d[0]), "+f"(d[1]), "+f"(d[2]), "+f"(d[3])
        : "r"(a[0]), "r"(a[1]), "r"(a[2]), "r"(a[3]), "r"(b[0]), "r"(b[1]));
}
static __device__ __forceinline__ void mma16808(float* d, const unsigned* a, unsigned b) {
    asm volatile(
        "mma.sync.aligned.m16n8k8.row.col.f32.f16.f16.f32 "
        "{%0,%1,%2,%3}, {%4,%5}, {%6}, {%0,%1,%2,%3};"
        : "+f"(d[0]), "+f"(d[1]), "+f"(d[2]), "+f"(d[3])
        : "r"(a[0]), "r"(a[1]), "r"(b));
}
static __device__ __forceinline__ void cpa16(unsigned dst, const void* src) {
    asm volatile("cp.async.cg.shared.global [%0], [%1], 16;" :: "r"(dst), "l"(src) : "memory");
}
static __device__ __forceinline__ void cpa4(unsigned dst, const void* src) {
    asm volatile("cp.async.ca.shared.global [%0], [%1], 4;" :: "r"(dst), "l"(src) : "memory");
}

// ---------------------------------------------------------------------------
// K3: triangular strips of 128x128 G-tiles (K = 128 + 8 aug), SJ=4.
// Identical mainloop/epilogue to R14 best; only a PDL grid-dep sync at entry.
// ---------------------------------------------------------------------------
__global__ void __launch_bounds__(256, 2)
main_kernel() {
    extern __shared__ char smem[];
    unsigned sb;
    asm("{ .reg .u64 t; cvta.to.shared.u64 t, %1; cvt.u32.u64 %0, t; }"
        : "=r"(sb) : "l"(smem));

    const int tid  = threadIdx.x;
    const int lane = tid & 31;
    const int wid  = tid >> 5;
    const int wm   = wid & 3;
    const int wn   = wid >> 2;

    // block -> (bi, strip)   (pre-sync: pure arithmetic)
    int rem = blockIdx.x, bi = 0;
    while (rem >= ((NB - bi + SJ - 1) >> 2)) { rem -= (NB - bi + SJ - 1) >> 2; bi++; }
    const int bj0   = bi + rem * SJ;
    const int ntile = min(SJ, NB - bj0);
    const int i0    = bi * 128;

    cudaGridDependencySynchronize();   // g_xh/g_aug/g_labS ready

    const uint4* xh4 = (const uint4*)g_xh;

    // --- prologue: A + Aaug + B0 + Baug0 + labJ0 ---
#pragma unroll
    for (int t = 0; t < 8; t++) {
        int idx = tid + t * 256;
        int row = idx >> 4, c = idx & 15;
        cpa16(sb + SM_A + row * 256 + ((c ^ (row & 7)) << 4),
              &xh4[((size_t)(i0 + row) << 4) + c]);
    }
    {
        int j0 = bj0 * 128;
#pragma unroll
        for (int t = 0; t < 8; t++) {
            int idx = tid + t * 256;
            int row = idx >> 4, c = idx & 15;
            cpa16(sb + SM_B0 + row * 256 + ((c ^ (row & 7)) << 4),
                  &xh4[((size_t)(j0 + row) << 4) + c]);
        }
        if (tid < 128) {
            cpa16(sb + SM_AAUG + tid * 16, &g_augA[i0 + tid]);
            cpa16(sb + SM_BAUG0 + tid * 16, &g_augB[j0 + tid]);
            cpa4(sb + SM_LABJ0 + tid * 4, &g_labS[j0 + tid]);
        }
    }
    asm volatile("cp.async.commit_group;" ::: "memory");

    // ldmatrix addressing
    const int aRow0 = wm * 32 + (lane & 15);
    const unsigned aBase0 = sb + SM_A + aRow0 * 256;
    const unsigned aBase1 = aBase0 + 16 * 256;
    const int aSw0 = aRow0 & 7, aSw1 = (aRow0 + 16) & 7;
    const int aCb  = lane >> 4;
    const int bRowL = wn * 64 + (lane & 7) + ((lane >> 4) << 3);
    const int bCb   = (lane >> 3) & 1;

    // per-thread row labels (sorted) + strip accumulators
    int li[2][2];
#pragma unroll
    for (int mt = 0; mt < 2; mt++)
#pragma unroll
        for (int p = 0; p < 2; p++)
            li[mt][p] = g_labS[i0 + wm * 32 + mt * 16 + (lane >> 2) + p * 8];
    const int labLastI = g_labS[i0 + 127];

    float gP[2][2], gN[2][2];   // min G over positives / max G over negatives
#pragma unroll
    for (int mt = 0; mt < 2; mt++)
#pragma unroll
        for (int p = 0; p < 2; p++) { gP[mt][p] = 1e30f; gN[mt][p] = -1e30f; }

    unsigned aA[2][2];

    for (int t = 0; t < ntile; t++) {
        asm volatile("cp.async.wait_group 0;" ::: "memory");
        __syncthreads();

        if (t == 0) {   // A-aug fragments are strip-constant
            ldm_x2(aA[0][0], aA[0][1], sb + SM_AAUG + (wm * 32 + (lane & 15)) * 16);
            ldm_x2(aA[1][0], aA[1][1], sb + SM_AAUG + (wm * 32 + 16 + (lane & 15)) * 16);
        }

        // prefetch next tile
        if (t + 1 < ntile) {
            int jn = (bj0 + t + 1) * 128;
            unsigned bdst = sb + (((t + 1) & 1) ? SM_B1 : SM_B0);
#pragma unroll
            for (int u = 0; u < 8; u++) {
                int idx = tid + u * 256;
                int row = idx >> 4, c = idx & 15;
                cpa16(bdst + row * 256 + ((c ^ (row & 7)) << 4),
                      &xh4[((size_t)(jn + row) << 4) + c]);
            }
            if (tid < 128) {
                cpa16(sb + (((t + 1) & 1) ? SM_BAUG1 : SM_BAUG0) + tid * 16, &g_augB[jn + tid]);
                cpa4(sb + (((t + 1) & 1) ? SM_LABJ1 : SM_LABJ0) + tid * 4, &g_labS[jn + tid]);
            }
            asm volatile("cp.async.commit_group;" ::: "memory");
        }

        const unsigned bB    = sb + ((t & 1) ? SM_B1 : SM_B0);
        const unsigned bAug  = sb + ((t & 1) ? SM_BAUG1 : SM_BAUG0);
        const int*     labJ  = (const int*)(smem + ((t & 1) ? SM_LABJ1 : SM_LABJ0));
        const int      j0t   = (bj0 + t) * 128;
        const bool     slow  = (labLastI >= g_labS[j0t]);   // label ranges overlap

        // --- mainloop: 8x k16 + 1x k8 aug ---
        float d[2][8][4];
#pragma unroll
        for (int mt = 0; mt < 2; mt++)
#pragma unroll
            for (int nt = 0; nt < 8; nt++)
#pragma unroll
                for (int r = 0; r < 4; r++) d[mt][nt][r] = 0.f;

#pragma unroll
        for (int ks = 0; ks < 8; ks++) {
            unsigned a[2][4];
            ldm_x4(a[0][0], a[0][1], a[0][2], a[0][3],
                   aBase0 + (((2 * ks + aCb) ^ aSw0) << 4));
            ldm_x4(a[1][0], a[1][1], a[1][2], a[1][3],
                   aBase1 + (((2 * ks + aCb) ^ aSw1) << 4));
            unsigned b[8][2];
#pragma unroll
            for (int ntp = 0; ntp < 4; ntp++) {
                int row = bRowL + ntp * 16;
                unsigned addr = bB + row * 256 + (((2 * ks + bCb) ^ (row & 7)) << 4);
                ldm_x4(b[2 * ntp][0], b[2 * ntp][1], b[2 * ntp + 1][0], b[2 * ntp + 1][1], addr);
            }
#pragma unroll
            for (int mt = 0; mt < 2; mt++)
#pragma unroll
                for (int nt = 0; nt < 8; nt++)
                    mma16816(d[mt][nt], a[mt], b[nt]);
        }
        {   // aug k8 step: adds -(sqi+sqj)/2
            unsigned bA[8];
            ldm_x4(bA[0], bA[1], bA[2], bA[3], bAug + (wn * 64 + lane) * 16);
            ldm_x4(bA[4], bA[5], bA[6], bA[7], bAug + (wn * 64 + 32 + lane) * 16);
#pragma unroll
            for (int mt = 0; mt < 2; mt++)
#pragma unroll
                for (int nt = 0; nt < 8; nt++)
                    mma16808(d[mt][nt], aA[mt], bA[nt]);
        }

        // --- epilogue ---
        if (!slow) {
#pragma unroll
            for (int nt = 0; nt < 8; nt++) {
                float cx0 = -1e30f, cx1 = -1e30f;
#pragma unroll
                for (int mt = 0; mt < 2; mt++) {
                    gN[mt][0] = fmaxf(gN[mt][0], fmaxf(d[mt][nt][0], d[mt][nt][1]));
                    gN[mt][1] = fmaxf(gN[mt][1], fmaxf(d[mt][nt][2], d[mt][nt][3]));
                    cx0 = fmaxf(cx0, fmaxf(d[mt][nt][0], d[mt][nt][2]));
                    cx1 = fmaxf(cx1, fmaxf(d[mt][nt][1], d[mt][nt][3]));
                }
#pragma unroll
                for (int off = 4; off <= 16; off <<= 1) {
                    cx0 = fmaxf(cx0, __shfl_xor_sync(0xffffffffu, cx0, off));
                    cx1 = fmaxf(cx1, __shfl_xor_sync(0xffffffffu, cx1, off));
                }
                if (lane < 4) {
                    int j = j0t + wn * 64 + nt * 8 + lane * 2;
                    atomicMin(&g_mm[j].y,     __float_as_uint(fmaxf(-2.f * cx0, 0.f)));
                    atomicMin(&g_mm[j + 1].y, __float_as_uint(fmaxf(-2.f * cx1, 0.f)));
                }
            }
        } else {
#pragma unroll
            for (int nt = 0; nt < 8; nt++) {
                int colb = wn * 64 + nt * 8 + (lane & 3) * 2;
                int lj0 = labJ[colb], lj1 = labJ[colb + 1];
                float cx0 = -1e30f, cx1 = -1e30f, cn0 = 1e30f, cn1 = 1e30f;
#pragma unroll
                for (int mt = 0; mt < 2; mt++)
#pragma unroll
                    for (int r = 0; r < 4; r++) {
                        int q = r & 1, p = r >> 1;
                        float g = d[mt][nt][r];
                        if ((q ? lj1 : lj0) == li[mt][p]) {
                            gP[mt][p] = fminf(gP[mt][p], g);
                            if (q) cn1 = fminf(cn1, g); else cn0 = fminf(cn0, g);
                        } else {
                            gN[mt][p] = fmaxf(gN[mt][p], g);
                            if (q) cx1 = fmaxf(cx1, g); else cx0 = fmaxf(cx0, g);
                        }
                    }
#pragma unroll
                for (int off = 4; off <= 16; off <<= 1) {
                    cx0 = fmaxf(cx0, __shfl_xor_sync(0xffffffffu, cx0, off));
                    cx1 = fmaxf(cx1, __shfl_xor_sync(0xffffffffu, cx1, off));
                    cn0 = fminf(cn0, __shfl_xor_sync(0xffffffffu, cn0, off));
                    cn1 = fminf(cn1, __shfl_xor_sync(0xffffffffu, cn1, off));
                }
                if (lane < 4) {
                    int j = j0t + wn * 64 + nt * 8 + lane * 2;
                    atomicMin(&g_mm[j].y,     __float_as_uint(fmaxf(-2.f * cx0, 0.f)));
                    atomicMin(&g_mm[j + 1].y, __float_as_uint(fmaxf(-2.f * cx1, 0.f)));
                    atomicMax(&g_mm[j].x,     __float_as_uint(fmaxf(-2.f * cn0, 0.f)));
                    atomicMax(&g_mm[j + 1].x, __float_as_uint(fmaxf(-2.f * cn1, 0.f)));
                }
            }
        }
    }

    // --- row-side final: reduce lane&3, combine wn via smem overlay on A ---
#pragma unroll
    for (int mt = 0; mt < 2; mt++)
#pragma unroll
        for (int p = 0; p < 2; p++) {
#pragma unroll
            for (int off = 1; off <= 2; off <<= 1) {
                gN[mt][p] = fmaxf(gN[mt][p], __shfl_xor_sync(0xffffffffu, gN[mt][p], off));
                gP[mt][p] = fminf(gP[mt][p], __shfl_xor_sync(0xffffffffu, gP[mt][p], off));
            }
        }
    float* rP = (float*)(smem);          // [2][128]
    float* rN = (float*)(smem + 1024);   // [2][128]
    __syncthreads();   // everyone past mainloop; A region reusable
    if ((lane & 3) == 0) {
#pragma unroll
        for (int mt = 0; mt < 2; mt++)
#pragma unroll
            for (int p = 0; p < 2; p++) {
                int row = wm * 32 + mt * 16 + (lane >> 2) + p * 8;
                rP[wn * 128 + row] = gP[mt][p];
                rN[wn * 128 + row] = gN[mt][p];
            }
    }
    __syncthreads();
    if (tid < 128) {
        float gp = fminf(rP[tid], rP[128 + tid]);
        float gn = fmaxf(rN[tid], rN[128 + tid]);
        atomicMax(&g_mm[i0 + tid].x, __float_as_uint(fmaxf(-2.f * gp, 0.f)));
        atomicMin(&g_mm[i0 + tid].y, __float_as_uint(fmaxf(-2.f * gn, 0.f)));
    }
}

// ---------------------------------------------------------------------------
// K4: loss = sum relu(maxpos - minneg + margin); deterministic single block
// ---------------------------------------------------------------------------
__global__ void final_kernel(float* __restrict__ out) {
    __shared__ float red[1024];
    cudaGridDependencySynchronize();   // g_mm ready
    float s = 0.f;
    for (int i = threadIdx.x; i < N; i += 1024) {
        uint2 mm = g_mm[i];
        float v = __uint_as_float(mm.x) - __uint_as_float(mm.y) + MARGIN;
        s += fmaxf(v, 0.f);
    }
    red[threadIdx.x] = s;
    __syncthreads();
#pragma unroll
    for (int w = 512; w > 0; w >>= 1) {
        if (threadIdx.x < w) red[threadIdx.x] += red[threadIdx.x + w];
        __syncthreads();
    }
    if (threadIdx.x == 0) out[0] = red[0];
}

extern "C" void kernel_launch(void* const* d_in, const int* in_sizes, int n_in,
                              void* d_out, int out_size) {
    const float* x   = (const float*)d_in[0];
    const int*   lab = (const int*)d_in[1];
    float*       out = (float*)d_out;

    cudaFuncSetAttribute(main_kernel, cudaFuncAttributeMaxDynamicSharedMemorySize, SMEM_TOTAL);

    // hist: plain primary launch
    hist_kernel<<<NCHUNK, 256>>>(lab);

    // PDL secondaries: may launch while their primary is still running;
    // each calls cudaGridDependencySynchronize() before touching upstream data.
    cudaLaunchAttribute pdl[1];
    pdl[0].id = cudaLaunchAttributeProgrammaticStreamSerialization;
    pdl[0].val.programmaticStreamSerializationAllowed = 1;

    {   // rank
        cudaLaunchConfig_t cfg = {};
        cfg.gridDim = dim3(NCHUNK); cfg.blockDim = dim3(256);
        cfg.attrs = pdl; cfg.numAttrs = 1;
        cudaLaunchKernelEx(&cfg, rank_kernel, lab);
    }
    {   // convert (phase-1 overlaps rank)
        cudaLaunchConfig_t cfg = {};
        cfg.gridDim = dim3(N * 16 / 256); cfg.blockDim = dim3(256);
        cfg.attrs = pdl; cfg.numAttrs = 1;
        cudaLaunchKernelEx(&cfg, convert_kernel, x);
    }
    {   // main (ramp overlaps convert tail)
        cudaLaunchConfig_t cfg = {};
        cfg.gridDim = dim3(NCTA); cfg.blockDim = dim3(256);
        cfg.dynamicSmemBytes = SMEM_TOTAL;
        cfg.attrs = pdl; cfg.numAttrs = 1;
        cudaLaunchKernelEx(&cfg, main_kernel);
    }
    {   // final (ramp overlaps main tail)
        cudaLaunchConfig_t cfg = {};
        cfg.gridDim = dim3(1); cfg.blockDim = dim3(1024);
        cfg.attrs = pdl; cfg.numAttrs = 1;
        cudaLaunchKernelEx(&cfg, final_kernel, out);
    }
}